// round 6
// baseline (speedup 1.0000x reference)
#include <cuda_runtime.h>

// fields: (B=64, H=512, W=512, C=6) float32
// pump_indices: (B, 2) int32
// out: (B, H, W, 4) float32 — per-sample mean of the 5x5 window over channels
//                             [2:6], broadcast over the whole (H, W) plane.
//
// Fused, barrier-free kernel, tuned for prologue dilution:
//   grid = (32, 64) = 2048 blocks x 256 thr -> 16384 warps (half of R5),
//   128 KB of stores per block, ~1.7 waves on 148 SMs.
//   Output stores use st.global.cs (streaming) so the 256 MB write stream
//   doesn't evict the per-sample window lines from L2 between graph replays
//   -> the per-warp prologue load chain runs at L2-hit latency.

#define H_DIM 512
#define W_DIM 512
#define C_DIM 6
#define RADIUS 2
#define WIN 5              // 2*RADIUS+1
#define WIN_PIX (WIN*WIN)  // 25
#define HW (H_DIM * W_DIM) // 262144 pixels per sample

#define FILL_THREADS 256
#define FILL_ITERS 32      // 256 thr * 32 * 16 B = 128 KB per block
// grid.x = HW / (FILL_THREADS * FILL_ITERS) = 32

__device__ __forceinline__ void st_cs_f4(float4* p, float4 v) {
    asm volatile("st.global.cs.v4.f32 [%0], {%1, %2, %3, %4};"
                 :: "l"(p), "f"(v.x), "f"(v.y), "f"(v.z), "f"(v.w)
                 : "memory");
}

__global__ void __launch_bounds__(FILL_THREADS)
fused_cs_kernel(const float* __restrict__ fields,
                const int* __restrict__ pump_indices,
                float4* __restrict__ out) {
    const int b = blockIdx.y;
    const int lane = threadIdx.x & 31;

    // ---- every warp: redundant window-mean computation (no barriers) ----
    const int py = __ldg(&pump_indices[2 * b + 0]);
    const int px = __ldg(&pump_indices[2 * b + 1]);

    float s0 = 0.f, s1 = 0.f, s2 = 0.f, s3 = 0.f;
    if (lane < WIN_PIX) {
        const int dy = lane / WIN;
        const int dx = lane % WIN;
        const int y = py - RADIUS + dy;
        const int x = px - RADIUS + dx;
        // channel offset 2 within a 6-float pixel -> 8-byte aligned
        const float* p = fields
            + ((size_t)b * HW + (size_t)y * W_DIM + x) * C_DIM + 2;
        float2 a = __ldg(reinterpret_cast<const float2*>(p));
        float2 c = __ldg(reinterpret_cast<const float2*>(p + 2));
        s0 = a.x; s1 = a.y; s2 = c.x; s3 = c.y;
    }

    // Butterfly reduce: all 32 lanes end with the full sum.
    #pragma unroll
    for (int off = 16; off > 0; off >>= 1) {
        s0 += __shfl_xor_sync(0xFFFFFFFFu, s0, off);
        s1 += __shfl_xor_sync(0xFFFFFFFFu, s1, off);
        s2 += __shfl_xor_sync(0xFFFFFFFFu, s2, off);
        s3 += __shfl_xor_sync(0xFFFFFFFFu, s3, off);
    }

    const float inv = 1.0f / (float)WIN_PIX;
    const float4 m = make_float4(s0 * inv, s1 * inv, s2 * inv, s3 * inv);

    // ---- streaming float4 store stream: 128 KB per block ----
    float4* dst = out + (size_t)b * HW
                      + (size_t)blockIdx.x * (FILL_THREADS * FILL_ITERS)
                      + threadIdx.x;
    #pragma unroll 8
    for (int i = 0; i < FILL_ITERS; ++i) {
        st_cs_f4(dst + i * FILL_THREADS, m);
    }
}

extern "C" void kernel_launch(void* const* d_in, const int* in_sizes, int n_in,
                              void* d_out, int out_size) {
    const float* fields = (const float*)d_in[0];
    const int* pump_indices = (const int*)d_in[1];
    float4* out = (float4*)d_out;

    const int B = in_sizes[1] / 2;  // (B, 2) int32

    dim3 grid(HW / (FILL_THREADS * FILL_ITERS), B);
    fused_cs_kernel<<<grid, FILL_THREADS>>>(fields, pump_indices, out);
}

// round 7
// speedup vs baseline: 1.0317x; 1.0317x over previous
#include <cuda_runtime.h>

// fields: (B=64, H=512, W=512, C=6) float32
// pump_indices: (B, 2) int32
// out: (B, H, W, 4) float32 — per-sample mean of the 5x5 window over channels
//                             [2:6], broadcast over the whole (H, W) plane.
//
// Fused, barrier-free kernel at the pure-fill geometry:
//   grid = (128, 64) = 8192 blocks x 256 thr, 32 KB of stores per block
//   (~7 waves on 148 SMs -> fine-grained self-balancing; this exact geometry
//   measured 38.7 us as a standalone fill).
//   Every warp redundantly computes its sample's 25-pixel window mean
//   (no smem / no __syncthreads), then streams coalesced float4 stores.
//   Measured excess over the fill floor shrinks monotonically with block
//   count (R4 1024: +5.4us, R6 2048: +3.9, R5 4096: +2.55) — imbalance, not
//   prologue, dominates; so use the finest-grained geometry.

#define H_DIM 512
#define W_DIM 512
#define C_DIM 6
#define RADIUS 2
#define WIN 5              // 2*RADIUS+1
#define WIN_PIX (WIN*WIN)  // 25
#define HW (H_DIM * W_DIM) // 262144 pixels per sample

#define FILL_THREADS 256
#define FILL_ITERS 8       // 256 thr * 8 * 16 B = 32 KB per block
// grid.x = HW / (FILL_THREADS * FILL_ITERS) = 128

__global__ void __launch_bounds__(FILL_THREADS)
fused_finegrain_kernel(const float* __restrict__ fields,
                       const int* __restrict__ pump_indices,
                       float4* __restrict__ out) {
    const int b = blockIdx.y;
    const int lane = threadIdx.x & 31;

    // ---- every warp: redundant window-mean computation (no barriers) ----
    const int py = __ldg(&pump_indices[2 * b + 0]);
    const int px = __ldg(&pump_indices[2 * b + 1]);

    float s0 = 0.f, s1 = 0.f, s2 = 0.f, s3 = 0.f;
    if (lane < WIN_PIX) {
        const int dy = lane / WIN;
        const int dx = lane % WIN;
        const int y = py - RADIUS + dy;
        const int x = px - RADIUS + dx;
        // channel offset 2 within a 6-float pixel -> 8-byte aligned
        const float* p = fields
            + ((size_t)b * HW + (size_t)y * W_DIM + x) * C_DIM + 2;
        float2 a = __ldg(reinterpret_cast<const float2*>(p));
        float2 c = __ldg(reinterpret_cast<const float2*>(p + 2));
        s0 = a.x; s1 = a.y; s2 = c.x; s3 = c.y;
    }

    // Butterfly reduce: all 32 lanes end with the full sum.
    #pragma unroll
    for (int off = 16; off > 0; off >>= 1) {
        s0 += __shfl_xor_sync(0xFFFFFFFFu, s0, off);
        s1 += __shfl_xor_sync(0xFFFFFFFFu, s1, off);
        s2 += __shfl_xor_sync(0xFFFFFFFFu, s2, off);
        s3 += __shfl_xor_sync(0xFFFFFFFFu, s3, off);
    }

    const float inv = 1.0f / (float)WIN_PIX;
    const float4 m = make_float4(s0 * inv, s1 * inv, s2 * inv, s3 * inv);

    // ---- coalesced float4 store stream: 32 KB per block ----
    float4* dst = out + (size_t)b * HW
                      + (size_t)blockIdx.x * (FILL_THREADS * FILL_ITERS)
                      + threadIdx.x;
    #pragma unroll
    for (int i = 0; i < FILL_ITERS; ++i) {
        dst[i * FILL_THREADS] = m;
    }
}

extern "C" void kernel_launch(void* const* d_in, const int* in_sizes, int n_in,
                              void* d_out, int out_size) {
    const float* fields = (const float*)d_in[0];
    const int* pump_indices = (const int*)d_in[1];
    float4* out = (float4*)d_out;

    const int B = in_sizes[1] / 2;  // (B, 2) int32

    dim3 grid(HW / (FILL_THREADS * FILL_ITERS), B);
    fused_finegrain_kernel<<<grid, FILL_THREADS>>>(fields, pump_indices, out);
}